// round 3
// baseline (speedup 1.0000x reference)
#include <cuda_runtime.h>

// Packed D matrix: out = u^T D v; each element duplicated as (d,d) in a 64-bit
// word for fma.rn.f32x2. Rows padded to 10 u64 (80B) so row starts are 16B-aligned.
__device__ unsigned long long g_Dp[90];

__device__ __forceinline__ unsigned long long pack2(float lo, float hi) {
    unsigned long long r;
    asm("mov.b64 %0, {%1, %2};" : "=l"(r) : "f"(lo), "f"(hi));
    return r;
}
__device__ __forceinline__ unsigned long long mul2(unsigned long long a, unsigned long long b) {
    unsigned long long d;
    asm("mul.rn.f32x2 %0, %1, %2;" : "=l"(d) : "l"(a), "l"(b));
    return d;
}
__device__ __forceinline__ unsigned long long fma2(unsigned long long a, unsigned long long b,
                                                   unsigned long long c) {
    unsigned long long d;
    asm("fma.rn.f32x2 %0, %1, %2, %3;" : "=l"(d) : "l"(a), "l"(b), "l"(c));
    return d;
}

// ---------------------------------------------------------------------------
// Prologue: build U (16x16) by evolving all 16 basis columns, form
// A = Re(U^dag Z0 U), transform to the 9x9 full-angle bilinear form D, pack.
// Fused gate G = RZ(c)RY(b)RX(a) = [[alpha, -conj(beta)],[beta, conj(alpha)]].
// Launch: <<<1, 128>>>.
// ---------------------------------------------------------------------------
__global__ void qnn_prologue(const float* __restrict__ w) {
    __shared__ float Sr[16][16];   // Sr[col][i] = Re(U[i][col])
    __shared__ float Si[16][16];
    __shared__ float sA[16][16];
    __shared__ float Gs[8][4];     // {ar, ai, br, bi} per (layer,wire)

    const int tid = threadIdx.x;   // 0..127
    const int col = tid >> 3;
    const int p   = tid & 7;

    Sr[col][p]     = (p == col) ? 1.f : 0.f;
    Sr[col][p + 8] = ((p + 8) == col) ? 1.f : 0.f;
    Si[col][p]     = 0.f;
    Si[col][p + 8] = 0.f;

    if (tid < 8) {
        float sa, ca, sb, cb, sc, cc;
        __sincosf(0.5f * w[3 * tid + 0], &sa, &ca);
        __sincosf(0.5f * w[3 * tid + 1], &sb, &cb);
        __sincosf(0.5f * w[3 * tid + 2], &sc, &cc);
        const float cbca = cb * ca, sbsa = sb * sa, sbca = sb * ca, cbsa = cb * sa;
        Gs[tid][0] = cc * cbca + sc * sbsa;   // ar
        Gs[tid][1] = cc * sbsa - sc * cbca;   // ai
        Gs[tid][2] = cc * sbca + sc * cbsa;   // br
        Gs[tid][3] = sc * sbca - cc * cbsa;   // bi
    }
    __syncthreads();

    // wire q <-> bit (3-q)
    for (int g = 0; g < 8; ++g) {
        const int q = g & 3;
        const int stride = 8 >> q;
        const int i0 = ((p & ~(stride - 1)) << 1) | (p & (stride - 1));
        const int i1 = i0 + stride;
        const float ar = Gs[g][0], ai = Gs[g][1], br = Gs[g][2], bi = Gs[g][3];
        const float a0r = Sr[col][i0], a0i = Si[col][i0];
        const float a1r = Sr[col][i1], a1i = Si[col][i1];
        Sr[col][i0] = ar * a0r - ai * a0i - br * a1r - bi * a1i;
        Si[col][i0] = ar * a0i + ai * a0r - br * a1i + bi * a1r;
        Sr[col][i1] = br * a0r - bi * a0i + ar * a1r + ai * a1i;
        Si[col][i1] = br * a0i + bi * a0r + ar * a1i - ai * a1r;
        __syncthreads();

        if (q == 3) {
            const int cw[4] = {0, 1, 2, 3};
            const int tw[4] = {1, 2, 3, 0};
            for (int k = 0; k < 4; ++k) {
                const int bc = 3 - cw[k], bt = 3 - tw[k];
                if (p < 4) {
                    int o0 = -1, o1 = -1;
                    for (int b = 0; b < 4; ++b)
                        if (b != bc && b != bt) { if (o0 < 0) o0 = b; else o1 = b; }
                    const int i = (1 << bc) | ((p & 1) << o0) | (((p >> 1) & 1) << o1);
                    const int j = i | (1 << bt);
                    float tr = Sr[col][i], ti = Si[col][i];
                    Sr[col][i] = Sr[col][j];  Si[col][i] = Si[col][j];
                    Sr[col][j] = tr;          Si[col][j] = ti;
                }
                __syncthreads();
            }
        }
    }

    for (int e = tid; e < 256; e += 128) {
        const int j = e >> 4, l = e & 15;
        float acc = 0.f;
        for (int i = 0; i < 16; ++i) {
            const float sgn = (i < 8) ? 1.f : -1.f;
            acc += sgn * (Sr[j][i] * Sr[l][i] + Si[j][i] * Si[l][i]);
        }
        sA[j][l] = acc;
    }
    __syncthreads();

    if (tid < 90) {
        const int a = tid / 10, b = tid % 10;
        float d = 0.f;
        if (b < 9) {
            const int t[4] = { a / 3, a % 3, b / 3, b % 3 };
            for (int k = 0; k < 16; ++k) {
                int j = 0, l = 0;
                float sgn = 1.f;
                for (int qq = 0; qq < 4; ++qq) {
                    const int kk = (k >> qq) & 1;
                    int jq, lq;
                    if (t[qq] == 2) { jq = kk; lq = 1 - kk; }
                    else            { jq = kk; lq = kk; if (t[qq] == 1 && kk) sgn = -sgn; }
                    j |= jq << (3 - qq);
                    l |= lq << (3 - qq);
                }
                d += sgn * sA[j][l];
            }
            d *= 0.0625f;
        }
        g_Dp[tid] = pack2(d, d);
    }
}

// ---------------------------------------------------------------------------
// Main: four samples per thread (two packed f32x2 streams), D from shared.
// ---------------------------------------------------------------------------
__global__ void __launch_bounds__(256) qnn_main(const float4* __restrict__ x4,
                                               float4* __restrict__ out, int nquad) {
    __shared__ __align__(16) unsigned long long sD[90];
    if (threadIdx.x < 45)
        ((ulonglong2*)sD)[threadIdx.x] = ((const ulonglong2*)g_Dp)[threadIdx.x];
    __syncthreads();

    const int idx = blockIdx.x * blockDim.x + threadIdx.x;
    if (idx >= nquad) return;

    const float4 xa = x4[4 * idx + 0];
    const float4 xb = x4[4 * idx + 1];
    const float4 xc = x4[4 * idx + 2];
    const float4 xd = x4[4 * idx + 3];

    float c0a, s0a, c1a, s1a, c2a, s2a, c3a, s3a;
    float c0b, s0b, c1b, s1b, c2b, s2b, c3b, s3b;
    float c0c, s0c, c1c, s1c, c2c, s2c, c3c, s3c;
    float c0d, s0d, c1d, s1d, c2d, s2d, c3d, s3d;
    __sincosf(xa.x, &s0a, &c0a);  __sincosf(xa.y, &s1a, &c1a);
    __sincosf(xa.z, &s2a, &c2a);  __sincosf(xa.w, &s3a, &c3a);
    __sincosf(xb.x, &s0b, &c0b);  __sincosf(xb.y, &s1b, &c1b);
    __sincosf(xb.z, &s2b, &c2b);  __sincosf(xb.w, &s3b, &c3b);
    __sincosf(xc.x, &s0c, &c0c);  __sincosf(xc.y, &s1c, &c1c);
    __sincosf(xc.z, &s2c, &c2c);  __sincosf(xc.w, &s3c, &c3c);
    __sincosf(xd.x, &s0d, &c0d);  __sincosf(xd.y, &s1d, &c1d);
    __sincosf(xd.z, &s2d, &c2d);  __sincosf(xd.w, &s3d, &c3d);

    // Stream A = samples (a,b), stream B = samples (c,d)
    unsigned long long puA[9], pvA[9], puB[9], pvB[9];
    {
        const unsigned long long pc0 = pack2(c0a, c0b), ps0 = pack2(s0a, s0b);
        const unsigned long long pc1 = pack2(c1a, c1b), ps1 = pack2(s1a, s1b);
        const unsigned long long pc2 = pack2(c2a, c2b), ps2 = pack2(s2a, s2b);
        const unsigned long long pc3 = pack2(c3a, c3b), ps3 = pack2(s3a, s3b);
        pvA[1] = pc3;             pvA[2] = ps3;
        pvA[3] = pc2;             pvA[4] = mul2(pc2, pc3);
        pvA[5] = mul2(pc2, ps3);  pvA[6] = ps2;
        pvA[7] = mul2(ps2, pc3);  pvA[8] = mul2(ps2, ps3);
        puA[1] = pc1;             puA[2] = ps1;
        puA[3] = pc0;             puA[4] = mul2(pc0, pc1);
        puA[5] = mul2(pc0, ps1);  puA[6] = ps0;
        puA[7] = mul2(ps0, pc1);  puA[8] = mul2(ps0, ps1);
    }
    {
        const unsigned long long pc0 = pack2(c0c, c0d), ps0 = pack2(s0c, s0d);
        const unsigned long long pc1 = pack2(c1c, c1d), ps1 = pack2(s1c, s1d);
        const unsigned long long pc2 = pack2(c2c, c2d), ps2 = pack2(s2c, s2d);
        const unsigned long long pc3 = pack2(c3c, c3d), ps3 = pack2(s3c, s3d);
        pvB[1] = pc3;             pvB[2] = ps3;
        pvB[3] = pc2;             pvB[4] = mul2(pc2, pc3);
        pvB[5] = mul2(pc2, ps3);  pvB[6] = ps2;
        pvB[7] = mul2(ps2, pc3);  pvB[8] = mul2(ps2, ps3);
        puB[1] = pc1;             puB[2] = ps1;
        puB[3] = pc0;             puB[4] = mul2(pc0, pc1);
        puB[5] = mul2(pc0, ps1);  puB[6] = ps0;
        puB[7] = mul2(ps0, pc1);  puB[8] = mul2(ps0, ps1);
    }

    unsigned long long accA = 0, accB = 0;
#pragma unroll
    for (int a = 0; a < 9; ++a) {
        const ulonglong2* row = reinterpret_cast<const ulonglong2*>(sD + a * 10);
        const ulonglong2 r0 = row[0], r1 = row[1], r2 = row[2], r3 = row[3];
        const unsigned long long d8 = sD[a * 10 + 8];

        unsigned long long dA = r0.x;                  // * v[0] == 1
        dA = fma2(r0.y, pvA[1], dA);
        dA = fma2(r1.x, pvA[2], dA);
        dA = fma2(r1.y, pvA[3], dA);
        dA = fma2(r2.x, pvA[4], dA);
        dA = fma2(r2.y, pvA[5], dA);
        dA = fma2(r3.x, pvA[6], dA);
        dA = fma2(r3.y, pvA[7], dA);
        dA = fma2(d8,   pvA[8], dA);

        unsigned long long dB = r0.x;
        dB = fma2(r0.y, pvB[1], dB);
        dB = fma2(r1.x, pvB[2], dB);
        dB = fma2(r1.y, pvB[3], dB);
        dB = fma2(r2.x, pvB[4], dB);
        dB = fma2(r2.y, pvB[5], dB);
        dB = fma2(r3.x, pvB[6], dB);
        dB = fma2(r3.y, pvB[7], dB);
        dB = fma2(d8,   pvB[8], dB);

        if (a == 0) { accA = dA; accB = dB; }          // * u[0] == 1
        else        { accA = fma2(puA[a], dA, accA);
                      accB = fma2(puB[a], dB, accB); }
    }

    float oa, ob, oc, od;
    asm("mov.b64 {%0, %1}, %2;" : "=f"(oa), "=f"(ob) : "l"(accA));
    asm("mov.b64 {%0, %1}, %2;" : "=f"(oc), "=f"(od) : "l"(accB));
    out[idx] = make_float4(oa, ob, oc, od);
}

extern "C" void kernel_launch(void* const* d_in, const int* in_sizes, int n_in,
                              void* d_out, int out_size) {
    const float* x = (const float*)d_in[0];
    const float* w = (const float*)d_in[1];
    float4* out = (float4*)d_out;
    const int B = out_size;
    const int nquad = B >> 2;

    qnn_prologue<<<1, 128>>>(w);
    const int blocks = (nquad + 255) / 256;
    qnn_main<<<blocks, 256>>>((const float4*)x, out, nquad);
}